// round 5
// baseline (speedup 1.0000x reference)
#include <cuda_runtime.h>
#include <math.h>

// Problem constants (from reference)
#define BQ 4
#define NQ 23
#define NPAIR 15
#define RLQ 32
#define ALQ 8
#define FEAT 1121   // 1 + 5*32 + 15*64

// cos/sin of theta grid: linspace(0, pi, 8) -> pi*t/7
__constant__ float CTH[8] = {
     1.0f,          0.90096886790f,  0.62348980186f,  0.22252093396f,
    -0.22252093396f, -0.62348980186f, -0.90096886790f, -1.0f };
__constant__ float STH[8] = {
     0.0f,          0.43388373912f,  0.78183148247f,  0.97492791218f,
     0.97492791218f, 0.78183148247f,  0.43388373912f,  0.0f };

__global__ __launch_bounds__(256, 1)
void ani_kernel(const float* __restrict__ coords,
                const int*   __restrict__ anum,
                float*       __restrict__ out)
{
    const int bi = blockIdx.x;
    const int b  = bi / NQ;
    const int i  = bi % NQ;
    const int tid  = threadIdx.x;
    const int w    = tid >> 5;
    const int lane = tid & 31;

    __shared__ float cx[NQ], cy[NQ], cz[NQ];
    __shared__ int   typ[NQ];
    __shared__ float dist[NQ], fac[NQ], frc[NQ];
    __shared__ int   nbr[NQ];
    __shared__ int   Msh;
    __shared__ float rad_acc[5 * RLQ];          // 160
    __shared__ float ang_acc[8][NPAIR * 64];    // 8 x 960 = 30720 B

    // ---- load coords (Bohr-scaled) and atom types for this batch ----
    if (tid < NQ) {
        const int j = tid;
        const float BOHR = 0.52917721092f;
        cx[j] = coords[(b * NQ + j) * 3 + 0] * BOHR;
        cy[j] = coords[(b * NQ + j) * 3 + 1] * BOHR;
        cz[j] = coords[(b * NQ + j) * 3 + 2] * BOHR;
        int z = anum[b * NQ + j];
        typ[j] = (z == 1) ? 0 : (z == 6) ? 1 : (z == 7) ? 2 :
                 (z == 8) ? 3 : (z == 16) ? 4 : -1;
    }
    __syncthreads();

    const float xi = cx[i], yi = cy[i], zi = cz[i];

    // ---- distances + cutoffs wrt atom i ----
    if (tid < NQ) {
        const int j = tid;
        float dx = cx[j] - xi, dy = cy[j] - yi, dz = cz[j] - zi;
        float dr = sqrtf(dx * dx + dy * dy + dz * dz + 1e-7f);
        dist[j] = dr;
        bool ne = (j != i);
        const float PI = 3.14159265358979323846f;
        frc[j] = (ne && dr < 4.6f) ? 0.5f * (cosf(PI * dr / 4.6f) + 1.0f) : 0.0f;
        fac[j] = (ne && dr < 3.1f) ? 0.5f * (cosf(PI * dr / 3.1f) + 1.0f) : 0.0f;
    }

    // ---- zero accumulators ----
    for (int f = tid; f < 5 * RLQ; f += 256) rad_acc[f] = 0.0f;
    {
        float* aa = &ang_acc[0][0];
        for (int f = tid; f < 8 * NPAIR * 64; f += 256) aa[f] = 0.0f;
    }
    __syncthreads();

    // ---- angular neighbor list (serial by thread 0: deterministic, tiny) ----
    if (tid == 0) {
        int m = 0;
        for (int j = 0; j < NQ; j++)
            if (fac[j] > 0.0f && typ[j] >= 0) nbr[m++] = j;
        Msh = m;
    }

    // ---- radial features: 32 threads, one r each (race-free SMEM adds) ----
    if (tid < 32) {
        const float rs   = (float)(4.6 * (double)tid / 31.0);
        const float step = (float)(4.6 / 31.0);
        const float ita  = 3.0f / (step * step);
        for (int j = 0; j < NQ; j++) {
            float fr = frc[j];
            int   t  = typ[j];
            if (fr > 0.0f && t >= 0) {
                float dd = dist[j] - rs;
                rad_acc[t * RLQ + tid] += expf(-ita * dd * dd) * fr;
            }
        }
    }
    __syncthreads();

    // ---- angular features ----
    // lane l-slots: l = lane and l = lane+32. (lane+32)&7 == lane&7, so the
    // theta factor (and the ^64 pow chain) is shared; only the radial-shell
    // Gaussian differs (rs index lane>>3 and lane>>3 + 4).
    {
        const int   thi  = lane & 7;
        const int   rsi  = lane >> 3;
        const float cth  = CTH[thi];
        const float sth  = STH[thi];
        const float rsa0 = (float)(3.1 * (double)rsi / 7.0);
        const float rsa1 = (float)(3.1 * (double)(rsi + 4) / 7.0);
        const float ITAA = (float)(147.0 / 9.61);   // 3/( (3.1/7)^2 )

        const int M = Msh;
        for (int pp = w; pp < M * M; pp += 8) {      // pp uniform per warp
            int j  = nbr[pp / M];
            int k  = nbr[pp % M];
            int tj = typ[j], tk = typ[k];
            if (tj > tk) continue;                    // only ordered type pairs exist
            int p = tj * 5 - (tj * (tj - 1)) / 2 + (tk - tj);

            float djx = cx[j] - xi, djy = cy[j] - yi, djz = cz[j] - zi;
            float dkx = cx[k] - xi, dky = cy[k] - yi, dkz = cz[k] - zi;
            float vm  = djx * dkx + djy * dky + djz * dkz;

            float ct   = vm / (dist[j] * dist[k] + 1e-5f);
            float st   = sqrtf(fmaxf(0.0f, 1.0f - ct * ct));
            float ravg = 0.5f * (dist[j] + dist[k]);
            float fp2  = 2.0f * fac[j] * fac[k];

            // a = ((1 + cos(theta - th_l))/2)^64 via identity + 6 squarings
            float a = 0.5f * (1.0f + ct * cth + st * sth);
            a = a * a; a = a * a; a = a * a;
            a = a * a; a = a * a; a = a * a;

            float d0 = ravg - rsa0;
            float d1 = ravg - rsa1;
            float g0 = expf(-ITAA * d0 * d0);
            float g1 = expf(-ITAA * d1 * d1);

            float* row = &ang_acc[w][p * 64];
            row[lane]      += a * g0 * fp2;
            row[lane + 32] += a * g1 * fp2;
        }
    }
    __syncthreads();

    // ---- reduce warp partials and write output ----
    const size_t base = (size_t)(b * NQ + i) * FEAT;
    if (tid == 0) out[base] = (float)anum[b * NQ + i];
    for (int f = tid; f < 5 * RLQ; f += 256)
        out[base + 1 + f] = rad_acc[f];
    for (int f = tid; f < NPAIR * 64; f += 256) {
        float s = 0.0f;
        #pragma unroll
        for (int ww = 0; ww < 8; ww++) s += ang_acc[ww][f];
        out[base + 1 + 5 * RLQ + f] = s;
    }
}

extern "C" void kernel_launch(void* const* d_in, const int* in_sizes, int n_in,
                              void* d_out, int out_size)
{
    const float* coords = (const float*)d_in[0];
    const int*   anum   = (const int*)d_in[1];
    float*       out    = (float*)d_out;
    ani_kernel<<<BQ * NQ, 256>>>(coords, anum, out);
}

// round 6
// speedup vs baseline: 1.4760x; 1.4760x over previous
#include <cuda_runtime.h>
#include <math.h>

// Problem constants
#define BQ 4
#define NQ 23
#define NPAIR 15
#define RLQ 32
#define FEAT 1121          // 1 + 5*32 + 15*64
#define NW 23              // one warp per j-row
#define NT (NW * 32)       // 736 threads
#define ANGW (NPAIR * 64)  // 960 floats per warp accumulator

// 0.5*cos(theta_l), 0.5*sin(theta_l), theta_l = pi*l/7
__constant__ float CTH2[8] = {
     0.5f,            0.45048443395f,  0.31174490093f,  0.11126046698f,
    -0.11126046698f, -0.31174490093f, -0.45048443395f, -0.5f };
__constant__ float STH2[8] = {
     0.0f,            0.21694186956f,  0.39091574124f,  0.48746395609f,
     0.48746395609f,  0.39091574124f,  0.21694186956f,  0.0f };

__global__ __launch_bounds__(NT, 1)
void ani_kernel(const float* __restrict__ coords,
                const int*   __restrict__ anum,
                float*       __restrict__ out)
{
    extern __shared__ float ang[];          // NW * 960 floats (88320 B)
    __shared__ float4 rel[NQ];              // (dx,dy,dz,dist) relative to atom i
    __shared__ float  fac[NQ], frc[NQ];
    __shared__ int    typ[NQ];
    __shared__ float  cxs[NQ], cys[NQ], czs[NQ];
    __shared__ float  rad_acc[5 * RLQ];

    const int bi = blockIdx.x;
    const int b  = bi / NQ;
    const int i  = bi % NQ;
    const int tid  = threadIdx.x;
    const int w    = tid >> 5;
    const int lane = tid & 31;

    // ---- load coords (Bohr) + types ----
    if (tid < NQ) {
        const int j = tid;
        const float BOHR = 0.52917721092f;
        cxs[j] = coords[(b * NQ + j) * 3 + 0] * BOHR;
        cys[j] = coords[(b * NQ + j) * 3 + 1] * BOHR;
        czs[j] = coords[(b * NQ + j) * 3 + 2] * BOHR;
        int z = anum[b * NQ + j];
        typ[j] = (z == 1) ? 0 : (z == 6) ? 1 : (z == 7) ? 2 :
                 (z == 8) ? 3 : (z == 16) ? 4 : -1;
    }
    __syncthreads();

    const float xi = cxs[i], yi = cys[i], zi = czs[i];

    // ---- relative vectors, distances, cutoffs ----
    if (tid < NQ) {
        const int j = tid;
        float dx = cxs[j] - xi, dy = cys[j] - yi, dz = czs[j] - zi;
        float dr = sqrtf(dx * dx + dy * dy + dz * dz + 1e-7f);
        rel[j] = make_float4(dx, dy, dz, dr);
        bool ne = (j != i);
        frc[j] = (ne && dr < 4.6f) ? 0.5f * (__cosf(0.68294733639181f * dr) + 1.0f) : 0.0f;
        fac[j] = (ne && dr < 3.1f) ? 0.5f * (__cosf(1.01341709287626f * dr) + 1.0f) : 0.0f;
    }

    // ---- zero accumulators ----
    for (int f = tid; f < 5 * RLQ; f += NT) rad_acc[f] = 0.0f;
    for (int f = tid; f < NW * ANGW; f += NT) ang[f] = 0.0f;
    __syncthreads();

    // ---- radial features: warp 0, one radial shell per lane (race-free) ----
    if (tid < 32) {
        const float step = 4.6f / 31.0f;
        const float rs   = step * (float)tid;
        const float nita = -3.0f / (step * step);
        for (int j = 0; j < NQ; j++) {
            float fr = frc[j];
            int   t  = typ[j];
            if (fr > 0.0f && t >= 0) {
                float dd = rel[j].w - rs;
                rad_acc[t * RLQ + tid] += __expf(nita * dd * dd) * fr;
            }
        }
    }

    // ---- angular features: warp w owns j = w ----
    {
        const int   j  = w;
        const float fj = fac[j];
        const int   tj = typ[j];
        if (fj > 0.0f && tj >= 0) {
            const float4 rj  = rel[j];
            const float  dj  = rj.w;
            const float  fj2 = 2.0f * fj;
            const float  djh = 0.5f * dj;
            const int    pjb = tj * 5 - (tj * (tj - 1)) / 2 - tj;  // p = pjb + tk
            float* accw = ang + w * ANGW;

            const int   thi  = lane & 7;
            const int   rsi  = lane >> 3;
            const float cth2 = CTH2[thi];
            const float sth2 = STH2[thi];
            const float ASTEP = 3.1f / 7.0f;
            const float rsa0  = ASTEP * (float)rsi;
            const float rsa1  = ASTEP * (float)(rsi + 4);
            const float NITA  = -3.0f / (ASTEP * ASTEP);

            #pragma unroll 1
            for (int kk = 0; kk < NQ; kk++) {
                const int   tk = typ[kk];
                const float fk = fac[kk];
                if (tk < tj || fk <= 0.0f) continue;   // ordered type pairs only

                const float4 rk = rel[kk];
                float vm = rj.x * rk.x + rj.y * rk.y + rj.z * rk.z;
                float ct = __fdividef(vm, fmaf(dj, rk.w, 1e-5f));
                float x  = fmaxf(1.0f - ct * ct, 0.0f);
                float st = x * rsqrtf(fmaxf(x, 1e-12f));   // sin(arccos(ct))

                // ((1 + cos(theta - th_l))/2)^64 via angle identity + 6 squarings
                float a = fmaf(ct, cth2, fmaf(st, sth2, 0.5f));
                a = a * a; a = a * a; a = a * a;
                a = a * a; a = a * a; a = a * a;

                float ravg = fmaf(rk.w, 0.5f, djh);
                float d0 = ravg - rsa0;
                float d1 = ravg - rsa1;
                float g0 = __expf(NITA * d0 * d0);
                float g1 = __expf(NITA * d1 * d1);

                float s = a * (fj2 * fk);
                float* row = accw + (pjb + tk) * 64;
                row[lane]      += s * g0;
                row[lane + 32] += s * g1;
            }
        }
    }
    __syncthreads();

    // ---- reduce warp partials + write output ----
    const size_t base = (size_t)(b * NQ + i) * FEAT;
    if (tid == 0) out[base] = (float)anum[b * NQ + i];
    for (int f = tid; f < 5 * RLQ; f += NT)
        out[base + 1 + f] = rad_acc[f];
    for (int f = tid; f < ANGW; f += NT) {
        float s = 0.0f;
        #pragma unroll
        for (int ww = 0; ww < NW; ww++) s += ang[ww * ANGW + f];
        out[base + 1 + 5 * RLQ + f] = s;
    }
}

extern "C" void kernel_launch(void* const* d_in, const int* in_sizes, int n_in,
                              void* d_out, int out_size)
{
    const float* coords = (const float*)d_in[0];
    const int*   anum   = (const int*)d_in[1];
    float*       out    = (float*)d_out;
    const size_t shmem = (size_t)NW * ANGW * sizeof(float);   // 88320 B
    cudaFuncSetAttribute(ani_kernel, cudaFuncAttributeMaxDynamicSharedMemorySize, (int)shmem);
    ani_kernel<<<BQ * NQ, NT, shmem>>>(coords, anum, out);
}